// round 1
// baseline (speedup 1.0000x reference)
#include <cuda_runtime.h>
#include <math.h>

// Problem constants
#define BB 4
#define SS 2048
#define DD 1024
#define HH 16
#define HD 64
#define MROWS (BB * SS)   // 8192

// Scratch (static device globals — allocation-free per harness rules)
__device__ float g_q[MROWS * DD];
__device__ float g_k[MROWS * DD];
__device__ float g_v[MROWS * DD];
__device__ float g_ctx[MROWS * DD];

// ---------------------------------------------------------------------------
// GEMM: C[M,N] = A[M,K] @ B[K,N] (+ bias). M=8192, N=K=1024.
// 64x64 block tile, 256 threads, 4x4 microtile, KT=16.
// ---------------------------------------------------------------------------
__global__ __launch_bounds__(256) void gemm64(const float* __restrict__ A,
                                              const float* __restrict__ Bm,
                                              const float* __restrict__ bias,
                                              float* __restrict__ C) {
    const int N = 1024, K = 1024;
    __shared__ float As[16][65];   // transposed: As[k][row]
    __shared__ float Bs[16][65];   // Bs[k][col]

    int t  = threadIdx.x;
    int tx = t & 15;
    int ty = t >> 4;
    int row0 = blockIdx.y * 64;
    int col0 = blockIdx.x * 64;

    float acc[4][4] = {};

    for (int tk = 0; tk < K; tk += 16) {
        // Load A tile (64 rows x 16 k), transposed into smem
        #pragma unroll
        for (int i = 0; i < 4; i++) {
            int idx = t + i * 256;          // 0..1023
            int k = idx & 15, r = idx >> 4; // k fast
            As[k][r] = A[(size_t)(row0 + r) * K + tk + k];
        }
        // Load B tile (16 k x 64 cols)
        #pragma unroll
        for (int i = 0; i < 4; i++) {
            int idx = t + i * 256;
            int c = idx & 63, k = idx >> 6; // c fast -> coalesced
            Bs[k][c] = Bm[(size_t)(tk + k) * N + col0 + c];
        }
        __syncthreads();

        #pragma unroll
        for (int kk = 0; kk < 16; kk++) {
            float a[4], b[4];
            #pragma unroll
            for (int i = 0; i < 4; i++) a[i] = As[kk][ty * 4 + i];
            #pragma unroll
            for (int j = 0; j < 4; j++) b[j] = Bs[kk][tx * 4 + j];
            #pragma unroll
            for (int i = 0; i < 4; i++)
                #pragma unroll
                for (int j = 0; j < 4; j++)
                    acc[i][j] += a[i] * b[j];
        }
        __syncthreads();
    }

    #pragma unroll
    for (int i = 0; i < 4; i++) {
        int r = row0 + ty * 4 + i;
        #pragma unroll
        for (int j = 0; j < 4; j++) {
            int c = col0 + tx * 4 + j;
            float v = acc[i][j];
            if (bias) v += bias[c];
            C[(size_t)r * N + c] = v;
        }
    }
}

// ---------------------------------------------------------------------------
// Flash-style causal attention, fp32.
// grid (S/64, H, B), 256 threads. Q tile = 64 rows, KV tiles of 64.
// smem: Qs[d][r] (transposed), KPs (K transposed, later aliased as P^T), Vs.
// ---------------------------------------------------------------------------
__global__ __launch_bounds__(256) void attn_kernel(const float* __restrict__ Q,
                                                   const float* __restrict__ K,
                                                   const float* __restrict__ V,
                                                   float* __restrict__ O) {
    extern __shared__ float sm[];
    float (*Qs)[65]  = (float (*)[65])sm;                 // [64][65]  Qs[d][r]
    float (*KPs)[65] = (float (*)[65])(sm + 64 * 65);     // Ks[d][j] / Ps[j][r]
    float (*Vs)[65]  = (float (*)[65])(sm + 2 * 64 * 65); // Vs[j][d]

    int t  = threadIdx.x;
    int tx = t & 15;
    int ty = t >> 4;
    int qb = blockIdx.x, h = blockIdx.y, b = blockIdx.z;
    int q0 = qb * 64;

    const float* Qbase = Q + (size_t)b * SS * DD + h * HD;
    const float* Kbase = K + (size_t)b * SS * DD + h * HD;
    const float* Vbase = V + (size_t)b * SS * DD + h * HD;

    // Load Q tile transposed: 4096 elements, 16 per thread
    #pragma unroll
    for (int i = 0; i < 16; i++) {
        int idx = t + i * 256;           // 0..4095
        int d = idx & 63, r = idx >> 6;  // d fast -> coalesced global read
        Qs[d][r] = Qbase[(size_t)(q0 + r) * DD + d];
    }

    float m[4], l[4], acc[4][4];
    #pragma unroll
    for (int i = 0; i < 4; i++) {
        m[i] = -3.0e38f; l[i] = 0.f;
        #pragma unroll
        for (int j = 0; j < 4; j++) acc[i][j] = 0.f;
    }
    const float sc = 0.125f;  // 1/sqrt(64)

    for (int kt = 0; kt <= qb; kt++) {
        int k0 = kt * 64;
        __syncthreads();  // covers Q load (1st iter) + P/V reads (prev iter)

        // Load K transposed + V direct
        #pragma unroll
        for (int i = 0; i < 16; i++) {
            int idx = t + i * 256;
            int d = idx & 63, j = idx >> 6;
            KPs[d][j] = Kbase[(size_t)(k0 + j) * DD + d];
            Vs[j][d]  = Vbase[(size_t)(k0 + j) * DD + d];
        }
        __syncthreads();

        // Scores: 4x4 microtile of S = Q K^T
        float s[4][4] = {};
        #pragma unroll 8
        for (int d = 0; d < 64; d++) {
            float a[4], bb[4];
            #pragma unroll
            for (int i = 0; i < 4; i++) a[i] = Qs[d][ty * 4 + i];
            #pragma unroll
            for (int j = 0; j < 4; j++) bb[j] = KPs[d][tx * 4 + j];
            #pragma unroll
            for (int i = 0; i < 4; i++)
                #pragma unroll
                for (int j = 0; j < 4; j++)
                    s[i][j] += a[i] * bb[j];
        }

        // Causal mask
        #pragma unroll
        for (int i = 0; i < 4; i++) {
            int qg = q0 + ty * 4 + i;
            #pragma unroll
            for (int j = 0; j < 4; j++) {
                int kg = k0 + tx * 4 + j;
                if (kg > qg) s[i][j] = -3.0e38f;
            }
        }

        // Online softmax (rows split across 16 tx lanes; same half-warp)
        float p[4][4];
        #pragma unroll
        for (int i = 0; i < 4; i++) {
            float rm = s[i][0];
            #pragma unroll
            for (int j = 1; j < 4; j++) rm = fmaxf(rm, s[i][j]);
            #pragma unroll
            for (int o = 1; o < 16; o <<= 1)
                rm = fmaxf(rm, __shfl_xor_sync(0xffffffffu, rm, o));
            float mnew = fmaxf(m[i], rm);
            float corr = __expf((m[i] - mnew) * sc);
            float ls = 0.f;
            #pragma unroll
            for (int j = 0; j < 4; j++) {
                p[i][j] = __expf((s[i][j] - mnew) * sc);
                ls += p[i][j];
            }
            #pragma unroll
            for (int o = 1; o < 16; o <<= 1)
                ls += __shfl_xor_sync(0xffffffffu, ls, o);
            l[i] = l[i] * corr + ls;
            m[i] = mnew;
            #pragma unroll
            for (int j = 0; j < 4; j++) acc[i][j] *= corr;
        }

        __syncthreads();  // all lanes done reading KPs-as-K before P overwrite
        // Write P transposed: Ps[j][r]
        #pragma unroll
        for (int i = 0; i < 4; i++)
            #pragma unroll
            for (int j = 0; j < 4; j++)
                KPs[tx * 4 + j][ty * 4 + i] = p[i][j];
        __syncthreads();

        // O += P @ V (4x4 microtile)
        #pragma unroll 8
        for (int j = 0; j < 64; j++) {
            float pv[4], vv[4];
            #pragma unroll
            for (int i = 0; i < 4; i++) pv[i] = KPs[j][ty * 4 + i];
            #pragma unroll
            for (int c = 0; c < 4; c++) vv[c] = Vs[j][tx * 4 + c];
            #pragma unroll
            for (int i = 0; i < 4; i++)
                #pragma unroll
                for (int c = 0; c < 4; c++)
                    acc[i][c] += pv[i] * vv[c];
        }
    }

    // Epilogue: normalize and write ctx[b, s, h, hd]
    float* Obase = O + (size_t)b * SS * DD + h * HD;
    #pragma unroll
    for (int i = 0; i < 4; i++) {
        float inv = 1.0f / l[i];
        int r = q0 + ty * 4 + i;
        #pragma unroll
        for (int c = 0; c < 4; c++)
            Obase[(size_t)r * DD + tx * 4 + c] = acc[i][c] * inv;
    }
}

// ---------------------------------------------------------------------------
extern "C" void kernel_launch(void* const* d_in, const int* in_sizes, int n_in,
                              void* d_out, int out_size) {
    const float* x  = (const float*)d_in[0];
    const float* Wq = (const float*)d_in[1];
    const float* Wk = (const float*)d_in[2];
    const float* Wv = (const float*)d_in[3];
    const float* Wo = (const float*)d_in[4];
    const float* bo = (const float*)d_in[5];
    float* out = (float*)d_out;

    float *q, *k, *v, *ctx;
    cudaGetSymbolAddress((void**)&q,   g_q);
    cudaGetSymbolAddress((void**)&k,   g_k);
    cudaGetSymbolAddress((void**)&v,   g_v);
    cudaGetSymbolAddress((void**)&ctx, g_ctx);

    dim3 ggrid(DD / 64, MROWS / 64);  // (16, 128)
    dim3 gblk(256);

    gemm64<<<ggrid, gblk>>>(x, Wq, nullptr, q);
    gemm64<<<ggrid, gblk>>>(x, Wk, nullptr, k);
    gemm64<<<ggrid, gblk>>>(x, Wv, nullptr, v);

    const int smem_bytes = 3 * 64 * 65 * (int)sizeof(float);  // 49920
    cudaFuncSetAttribute(attn_kernel,
                         cudaFuncAttributeMaxDynamicSharedMemorySize, smem_bytes);
    attn_kernel<<<dim3(SS / 64, HH, BB), 256, smem_bytes>>>(q, k, v, ctx);

    gemm64<<<ggrid, gblk>>>(ctx, Wo, bo, out);
}

// round 3
// speedup vs baseline: 2.0012x; 2.0012x over previous
#include <cuda_runtime.h>
#include <math.h>
#include <stdint.h>

// Problem constants
#define BB 4
#define SS 2048
#define DD 1024
#define HH 16
#define HD 64
#define MROWS (BB * SS)   // 8192

// Scratch (static device globals — allocation-free per harness rules)
__device__ float g_q[MROWS * DD];
__device__ float g_k[MROWS * DD];
__device__ float g_v[MROWS * DD];
__device__ float g_ctx[MROWS * DD];
__device__ float g_wt[4][DD * DD];   // transposed weights [N][K]

extern __shared__ char dynsmem[];

__device__ __forceinline__ uint32_t f2tf32(float f) {
    uint32_t r;
    asm("cvt.rna.tf32.f32 %0, %1;" : "=r"(r) : "f"(f));
    return r;
}

__device__ __forceinline__ void mma_tf32(float* d, const uint32_t* a, const uint32_t* b) {
    asm volatile(
        "mma.sync.aligned.m16n8k8.row.col.f32.tf32.tf32.f32 "
        "{%0,%1,%2,%3}, {%4,%5,%6,%7}, {%8,%9}, {%0,%1,%2,%3};"
        : "+f"(d[0]), "+f"(d[1]), "+f"(d[2]), "+f"(d[3])
        : "r"(a[0]), "r"(a[1]), "r"(a[2]), "r"(a[3]), "r"(b[0]), "r"(b[1]));
}

// ---------------------------------------------------------------------------
// Weight transpose: out[n*K+k] = in[k*N+n], 1024x1024
// ---------------------------------------------------------------------------
__global__ void transpose1024(const float* __restrict__ in, float* __restrict__ out) {
    __shared__ float t[32][33];
    int x = blockIdx.x * 32 + threadIdx.x;
    int y = blockIdx.y * 32 + threadIdx.y;
    #pragma unroll
    for (int j = 0; j < 32; j += 8)
        t[threadIdx.y + j][threadIdx.x] = in[(size_t)(y + j) * DD + x];
    __syncthreads();
    x = blockIdx.y * 32 + threadIdx.x;
    y = blockIdx.x * 32 + threadIdx.y;
    #pragma unroll
    for (int j = 0; j < 32; j += 8)
        out[(size_t)(y + j) * DD + x] = t[threadIdx.x][threadIdx.y + j];
}

// ---------------------------------------------------------------------------
// TF32 mma.sync GEMM: C[M,N] = A[M,K] @ Bt[N,K]^T (+ bias)
// BM=128, BN=128, BK=32. 256 threads = 8 warps (2 M x 4 N), warp tile 64x32.
// m16n8k8 tiles: 4 (M) x 4 (N) per warp per k8-step.
// ---------------------------------------------------------------------------
#define GK 1024
#define GN 1024
#define PAD 36   // 32 + 4: makes fragment loads conflict-free (4g+t mod 32)

__global__ __launch_bounds__(256) void gemm_tc(const float* __restrict__ A,
                                               const float* __restrict__ Bt,
                                               const float* __restrict__ bias,
                                               float* __restrict__ C) {
    __shared__ uint32_t As[128 * PAD];
    __shared__ uint32_t Bs[128 * PAD];

    const int t     = threadIdx.x;
    const int lane  = t & 31;
    const int wid   = t >> 5;
    const int wm    = wid & 1;          // 0..1  (M)
    const int wn    = wid >> 1;         // 0..3  (N)
    const int g     = lane >> 2;        // group 0..7
    const int tig   = lane & 3;         // thread-in-group 0..3

    const int row0 = blockIdx.y * 128;
    const int col0 = blockIdx.x * 128;

    // global load mapping: 1024 float4 per tile, 4 per thread
    const int c4 = t & 7;               // 16B unit in 32-float row
    const int r0 = t >> 3;              // 0..31, rows r0 + 32*i

    float acc[4][4][4];
    #pragma unroll
    for (int mt = 0; mt < 4; mt++)
        #pragma unroll
        for (int nt = 0; nt < 4; nt++)
            #pragma unroll
            for (int i = 0; i < 4; i++) acc[mt][nt][i] = 0.f;

    for (int kb = 0; kb < GK; kb += 32) {
        // Load + convert tiles
        #pragma unroll
        for (int i = 0; i < 4; i++) {
            int r = r0 + i * 32;
            float4 va = *(const float4*)(A  + (size_t)(row0 + r) * GK + kb + c4 * 4);
            float4 vb = *(const float4*)(Bt + (size_t)(col0 + r) * GK + kb + c4 * 4);
            uint32_t* pa = &As[r * PAD + c4 * 4];
            uint32_t* pb = &Bs[r * PAD + c4 * 4];
            *(uint4*)pa = make_uint4(f2tf32(va.x), f2tf32(va.y), f2tf32(va.z), f2tf32(va.w));
            *(uint4*)pb = make_uint4(f2tf32(vb.x), f2tf32(vb.y), f2tf32(vb.z), f2tf32(vb.w));
        }
        __syncthreads();

        #pragma unroll
        for (int kk = 0; kk < 32; kk += 8) {
            uint32_t af[4][4], bf[4][2];
            #pragma unroll
            for (int mt = 0; mt < 4; mt++) {
                int rbase = wm * 64 + mt * 16;
                af[mt][0] = As[(rbase + g) * PAD + kk + tig];
                af[mt][1] = As[(rbase + g + 8) * PAD + kk + tig];
                af[mt][2] = As[(rbase + g) * PAD + kk + tig + 4];
                af[mt][3] = As[(rbase + g + 8) * PAD + kk + tig + 4];
            }
            #pragma unroll
            for (int nt = 0; nt < 4; nt++) {
                int nbase = wn * 32 + nt * 8;
                bf[nt][0] = Bs[(nbase + g) * PAD + kk + tig];
                bf[nt][1] = Bs[(nbase + g) * PAD + kk + tig + 4];
            }
            #pragma unroll
            for (int mt = 0; mt < 4; mt++)
                #pragma unroll
                for (int nt = 0; nt < 4; nt++)
                    mma_tf32(acc[mt][nt], af[mt], bf[nt]);
        }
        __syncthreads();
    }

    // Epilogue: c0,c1 at (row=g, col=2*tig), c2,c3 at (row=g+8, col=2*tig)
    #pragma unroll
    for (int mt = 0; mt < 4; mt++) {
        #pragma unroll
        for (int nt = 0; nt < 4; nt++) {
            int r1 = row0 + wm * 64 + mt * 16 + g;
            int cc = col0 + wn * 32 + nt * 8 + 2 * tig;
            float2 o0 = make_float2(acc[mt][nt][0], acc[mt][nt][1]);
            float2 o1 = make_float2(acc[mt][nt][2], acc[mt][nt][3]);
            if (bias) {
                float2 bv = *(const float2*)(bias + cc);
                o0.x += bv.x; o0.y += bv.y;
                o1.x += bv.x; o1.y += bv.y;
            }
            *(float2*)(C + (size_t)r1 * GN + cc)       = o0;
            *(float2*)(C + (size_t)(r1 + 8) * GN + cc) = o1;
        }
    }
}

// ---------------------------------------------------------------------------
// Flash-style causal attention, fp32 (unchanged).
// ---------------------------------------------------------------------------
__global__ __launch_bounds__(256) void attn_kernel(const float* __restrict__ Q,
                                                   const float* __restrict__ K,
                                                   const float* __restrict__ V,
                                                   float* __restrict__ O) {
    float* sm = (float*)dynsmem;
    float (*Qs)[65]  = (float (*)[65])sm;                 // [64][65]  Qs[d][r]
    float (*KPs)[65] = (float (*)[65])(sm + 64 * 65);     // Ks[d][j] / Ps[j][r]
    float (*Vs)[65]  = (float (*)[65])(sm + 2 * 64 * 65); // Vs[j][d]

    int t  = threadIdx.x;
    int tx = t & 15;
    int ty = t >> 4;
    int qb = blockIdx.x, h = blockIdx.y, b = blockIdx.z;
    int q0 = qb * 64;

    const float* Qbase = Q + (size_t)b * SS * DD + h * HD;
    const float* Kbase = K + (size_t)b * SS * DD + h * HD;
    const float* Vbase = V + (size_t)b * SS * DD + h * HD;

    #pragma unroll
    for (int i = 0; i < 16; i++) {
        int idx = t + i * 256;
        int d = idx & 63, r = idx >> 6;
        Qs[d][r] = Qbase[(size_t)(q0 + r) * DD + d];
    }

    float m[4], l[4], acc[4][4];
    #pragma unroll
    for (int i = 0; i < 4; i++) {
        m[i] = -3.0e38f; l[i] = 0.f;
        #pragma unroll
        for (int j = 0; j < 4; j++) acc[i][j] = 0.f;
    }
    const float sc = 0.125f;

    for (int kt = 0; kt <= qb; kt++) {
        int k0 = kt * 64;
        __syncthreads();

        #pragma unroll
        for (int i = 0; i < 16; i++) {
            int idx = t + i * 256;
            int d = idx & 63, j = idx >> 6;
            KPs[d][j] = Kbase[(size_t)(k0 + j) * DD + d];
            Vs[j][d]  = Vbase[(size_t)(k0 + j) * DD + d];
        }
        __syncthreads();

        float s[4][4] = {};
        #pragma unroll 8
        for (int d = 0; d < 64; d++) {
            float a[4], bb[4];
            #pragma unroll
            for (int i = 0; i < 4; i++) a[i] = Qs[d][ty * 4 + i];
            #pragma unroll
            for (int j = 0; j < 4; j++) bb[j] = KPs[d][tx * 4 + j];
            #pragma unroll
            for (int i = 0; i < 4; i++)
                #pragma unroll
                for (int j = 0; j < 4; j++)
                    s[i][j] += a[i] * bb[j];
        }

        #pragma unroll
        for (int i = 0; i < 4; i++) {
            int qg = q0 + ty * 4 + i;
            #pragma unroll
            for (int j = 0; j < 4; j++) {
                int kg = k0 + tx * 4 + j;
                if (kg > qg) s[i][j] = -3.0e38f;
            }
        }

        float p[4][4];
        #pragma unroll
        for (int i = 0; i < 4; i++) {
            float rm = s[i][0];
            #pragma unroll
            for (int j = 1; j < 4; j++) rm = fmaxf(rm, s[i][j]);
            #pragma unroll
            for (int o = 1; o < 16; o <<= 1)
                rm = fmaxf(rm, __shfl_xor_sync(0xffffffffu, rm, o));
            float mnew = fmaxf(m[i], rm);
            float corr = __expf((m[i] - mnew) * sc);
            float ls = 0.f;
            #pragma unroll
            for (int j = 0; j < 4; j++) {
                p[i][j] = __expf((s[i][j] - mnew) * sc);
                ls += p[i][j];
            }
            #pragma unroll
            for (int o = 1; o < 16; o <<= 1)
                ls += __shfl_xor_sync(0xffffffffu, ls, o);
            l[i] = l[i] * corr + ls;
            m[i] = mnew;
            #pragma unroll
            for (int j = 0; j < 4; j++) acc[i][j] *= corr;
        }

        __syncthreads();
        #pragma unroll
        for (int i = 0; i < 4; i++)
            #pragma unroll
            for (int j = 0; j < 4; j++)
                KPs[tx * 4 + j][ty * 4 + i] = p[i][j];
        __syncthreads();

        #pragma unroll 8
        for (int j = 0; j < 64; j++) {
            float pv[4], vv[4];
            #pragma unroll
            for (int i = 0; i < 4; i++) pv[i] = KPs[j][ty * 4 + i];
            #pragma unroll
            for (int c = 0; c < 4; c++) vv[c] = Vs[j][tx * 4 + c];
            #pragma unroll
            for (int i = 0; i < 4; i++)
                #pragma unroll
                for (int c = 0; c < 4; c++)
                    acc[i][c] += pv[i] * vv[c];
        }
    }

    float* Obase = O + (size_t)b * SS * DD + h * HD;
    #pragma unroll
    for (int i = 0; i < 4; i++) {
        float inv = 1.0f / l[i];
        int r = q0 + ty * 4 + i;
        #pragma unroll
        for (int c = 0; c < 4; c++)
            Obase[(size_t)r * DD + tx * 4 + c] = acc[i][c] * inv;
    }
}

// ---------------------------------------------------------------------------
extern "C" void kernel_launch(void* const* d_in, const int* in_sizes, int n_in,
                              void* d_out, int out_size) {
    const float* x  = (const float*)d_in[0];
    const float* Wq = (const float*)d_in[1];
    const float* Wk = (const float*)d_in[2];
    const float* Wv = (const float*)d_in[3];
    const float* Wo = (const float*)d_in[4];
    const float* bo = (const float*)d_in[5];
    float* out = (float*)d_out;

    float *q, *k, *v, *ctx, *wt;
    cudaGetSymbolAddress((void**)&q,   g_q);
    cudaGetSymbolAddress((void**)&k,   g_k);
    cudaGetSymbolAddress((void**)&v,   g_v);
    cudaGetSymbolAddress((void**)&ctx, g_ctx);
    cudaGetSymbolAddress((void**)&wt,  g_wt);
    float* WqT = wt;
    float* WkT = wt + 1 * DD * DD;
    float* WvT = wt + 2 * DD * DD;
    float* WoT = wt + 3 * DD * DD;

    dim3 tgrid(32, 32), tblk(32, 8);
    transpose1024<<<tgrid, tblk>>>(Wq, WqT);
    transpose1024<<<tgrid, tblk>>>(Wk, WkT);
    transpose1024<<<tgrid, tblk>>>(Wv, WvT);
    transpose1024<<<tgrid, tblk>>>(Wo, WoT);

    dim3 ggrid(GN / 128, MROWS / 128);  // (8, 64)
    gemm_tc<<<ggrid, 256>>>(x, WqT, nullptr, q);
    gemm_tc<<<ggrid, 256>>>(x, WkT, nullptr, k);
    gemm_tc<<<ggrid, 256>>>(x, WvT, nullptr, v);

    const int attn_smem = 3 * 64 * 65 * (int)sizeof(float);  // 49920
    cudaFuncSetAttribute(attn_kernel, cudaFuncAttributeMaxDynamicSharedMemorySize, attn_smem);
    attn_kernel<<<dim3(SS / 64, HH, BB), 256, attn_smem>>>(q, k, v, ctx);

    gemm_tc<<<ggrid, 256>>>(ctx, WoT, bo, out);
}

// round 4
// speedup vs baseline: 4.2762x; 2.1369x over previous
#include <cuda_runtime.h>
#include <math.h>
#include <stdint.h>

// Problem constants
#define BB 4
#define SS 2048
#define DD 1024
#define HH 16
#define HD 64
#define MROWS (BB * SS)   // 8192

// Scratch (static device globals — allocation-free per harness rules)
__device__ float g_q[MROWS * DD];
__device__ float g_k[MROWS * DD];
__device__ float g_v[MROWS * DD];
__device__ float g_ctx[MROWS * DD];
__device__ float g_wt[4][DD * DD];   // transposed weights [N][K]

extern __shared__ char dynsmem[];

__device__ __forceinline__ uint32_t f2tf32(float f) {
    uint32_t r;
    asm("cvt.rna.tf32.f32 %0, %1;" : "=r"(r) : "f"(f));
    return r;
}

__device__ __forceinline__ void mma_tf32(float* d, const uint32_t* a, const uint32_t* b) {
    asm volatile(
        "mma.sync.aligned.m16n8k8.row.col.f32.tf32.tf32.f32 "
        "{%0,%1,%2,%3}, {%4,%5,%6,%7}, {%8,%9}, {%0,%1,%2,%3};"
        : "+f"(d[0]), "+f"(d[1]), "+f"(d[2]), "+f"(d[3])
        : "r"(a[0]), "r"(a[1]), "r"(a[2]), "r"(a[3]), "r"(b[0]), "r"(b[1]));
}

// ---------------------------------------------------------------------------
// Weight transpose: out[n*K+k] = in[k*N+n], 1024x1024
// ---------------------------------------------------------------------------
__global__ void transpose1024(const float* __restrict__ in, float* __restrict__ out) {
    __shared__ float t[32][33];
    int x = blockIdx.x * 32 + threadIdx.x;
    int y = blockIdx.y * 32 + threadIdx.y;
    #pragma unroll
    for (int j = 0; j < 32; j += 8)
        t[threadIdx.y + j][threadIdx.x] = in[(size_t)(y + j) * DD + x];
    __syncthreads();
    x = blockIdx.y * 32 + threadIdx.x;
    y = blockIdx.x * 32 + threadIdx.y;
    #pragma unroll
    for (int j = 0; j < 32; j += 8)
        out[(size_t)(y + j) * DD + x] = t[threadIdx.x][threadIdx.y + j];
}

// ---------------------------------------------------------------------------
// TF32 mma.sync GEMM: C[M,N] = A[M,K] @ Bt[N,K]^T (+ bias)  (round-3, passing)
// ---------------------------------------------------------------------------
#define GK 1024
#define GN 1024
#define PAD 36

__global__ __launch_bounds__(256) void gemm_tc(const float* __restrict__ A,
                                               const float* __restrict__ Bt,
                                               const float* __restrict__ bias,
                                               float* __restrict__ C) {
    __shared__ uint32_t As[128 * PAD];
    __shared__ uint32_t Bs[128 * PAD];

    const int t    = threadIdx.x;
    const int lane = t & 31;
    const int wid  = t >> 5;
    const int wm   = wid & 1;
    const int wn   = wid >> 1;
    const int g    = lane >> 2;
    const int tig  = lane & 3;

    const int row0 = blockIdx.y * 128;
    const int col0 = blockIdx.x * 128;

    const int c4 = t & 7;
    const int r0 = t >> 3;

    float acc[4][4][4];
    #pragma unroll
    for (int mt = 0; mt < 4; mt++)
        #pragma unroll
        for (int nt = 0; nt < 4; nt++)
            #pragma unroll
            for (int i = 0; i < 4; i++) acc[mt][nt][i] = 0.f;

    for (int kb = 0; kb < GK; kb += 32) {
        #pragma unroll
        for (int i = 0; i < 4; i++) {
            int r = r0 + i * 32;
            float4 va = *(const float4*)(A  + (size_t)(row0 + r) * GK + kb + c4 * 4);
            float4 vb = *(const float4*)(Bt + (size_t)(col0 + r) * GK + kb + c4 * 4);
            *(uint4*)&As[r * PAD + c4 * 4] =
                make_uint4(f2tf32(va.x), f2tf32(va.y), f2tf32(va.z), f2tf32(va.w));
            *(uint4*)&Bs[r * PAD + c4 * 4] =
                make_uint4(f2tf32(vb.x), f2tf32(vb.y), f2tf32(vb.z), f2tf32(vb.w));
        }
        __syncthreads();

        #pragma unroll
        for (int kk = 0; kk < 32; kk += 8) {
            uint32_t af[4][4], bf[4][2];
            #pragma unroll
            for (int mt = 0; mt < 4; mt++) {
                int rbase = wm * 64 + mt * 16;
                af[mt][0] = As[(rbase + g) * PAD + kk + tig];
                af[mt][1] = As[(rbase + g + 8) * PAD + kk + tig];
                af[mt][2] = As[(rbase + g) * PAD + kk + tig + 4];
                af[mt][3] = As[(rbase + g + 8) * PAD + kk + tig + 4];
            }
            #pragma unroll
            for (int nt = 0; nt < 4; nt++) {
                int nbase = wn * 32 + nt * 8;
                bf[nt][0] = Bs[(nbase + g) * PAD + kk + tig];
                bf[nt][1] = Bs[(nbase + g) * PAD + kk + tig + 4];
            }
            #pragma unroll
            for (int mt = 0; mt < 4; mt++)
                #pragma unroll
                for (int nt = 0; nt < 4; nt++)
                    mma_tf32(acc[mt][nt], af[mt], bf[nt]);
        }
        __syncthreads();
    }

    #pragma unroll
    for (int mt = 0; mt < 4; mt++) {
        #pragma unroll
        for (int nt = 0; nt < 4; nt++) {
            int r1 = row0 + wm * 64 + mt * 16 + g;
            int cc = col0 + wn * 32 + nt * 8 + 2 * tig;
            float2 o0 = make_float2(acc[mt][nt][0], acc[mt][nt][1]);
            float2 o1 = make_float2(acc[mt][nt][2], acc[mt][nt][3]);
            if (bias) {
                float2 bv = *(const float2*)(bias + cc);
                o0.x += bv.x; o0.y += bv.y;
                o1.x += bv.x; o1.y += bv.y;
            }
            *(float2*)(C + (size_t)r1 * GN + cc)       = o0;
            *(float2*)(C + (size_t)(r1 + 8) * GN + cc) = o1;
        }
    }
}

// ---------------------------------------------------------------------------
// Tensor-core flash attention (tf32 mma.sync), causal.
// Block: 128 Q rows x one (b,h). 256 threads = 8 warps, 16 Q rows per warp.
// KV tiles of 64. Q/K smem pad 68, V pad 72 (conflict-free per access pattern).
// ---------------------------------------------------------------------------
#define QPAD 68
#define VPAD 72
#define ATTN_SMEM ((128 * QPAD + 64 * QPAD + 64 * VPAD) * 4)

__global__ __launch_bounds__(256, 2) void attn_tc(const float* __restrict__ Q,
                                                  const float* __restrict__ K,
                                                  const float* __restrict__ V,
                                                  float* __restrict__ O) {
    uint32_t* Qs = (uint32_t*)dynsmem;           // [128][QPAD]
    uint32_t* Ks = Qs + 128 * QPAD;              // [64][QPAD]
    uint32_t* Vs = Ks + 64 * QPAD;               // [64][VPAD]

    const int t    = threadIdx.x;
    const int lane = t & 31;
    const int wid  = t >> 5;          // 0..7
    const int g    = lane >> 2;       // 0..7
    const int tig  = lane & 3;        // 0..3

    const int qb = gridDim.x - 1 - blockIdx.x;   // big blocks first
    const int h  = blockIdx.y, b = blockIdx.z;
    const int q0 = qb * 128;

    const float* Qbase = Q + (size_t)b * SS * DD + h * HD;
    const float* Kbase = K + (size_t)b * SS * DD + h * HD;
    const float* Vbase = V + (size_t)b * SS * DD + h * HD;

    // Stage Q tile (128x64), tf32, pre-scaled by 1/8
    {
        const float sc = 0.125f;
        #pragma unroll
        for (int i = 0; i < 8; i++) {
            int idx = t + i * 256;        // 0..2047
            int row = idx >> 4, c4 = idx & 15;
            float4 v = *(const float4*)(Qbase + (size_t)(q0 + row) * DD + c4 * 4);
            *(uint4*)&Qs[row * QPAD + c4 * 4] =
                make_uint4(f2tf32(v.x * sc), f2tf32(v.y * sc),
                           f2tf32(v.z * sc), f2tf32(v.w * sc));
        }
    }

    float o[8][4];
    #pragma unroll
    for (int dt = 0; dt < 8; dt++)
        #pragma unroll
        for (int i = 0; i < 4; i++) o[dt][i] = 0.f;
    float m0 = -1e30f, m1 = -1e30f, l0 = 0.f, l1 = 0.f;

    const int qrow = wid * 16;
    const int ntiles = 2 * qb + 2;

    for (int kt = 0; kt < ntiles; kt++) {
        const int k0 = kt * 64;
        __syncthreads();   // covers Q stage (first iter) + K/V reuse

        // Load K,V tile (64x64 each)
        #pragma unroll
        for (int i = 0; i < 4; i++) {
            int idx = t + i * 256;        // 0..1023
            int row = idx >> 4, c4 = idx & 15;
            float4 kv = *(const float4*)(Kbase + (size_t)(k0 + row) * DD + c4 * 4);
            float4 vv = *(const float4*)(Vbase + (size_t)(k0 + row) * DD + c4 * 4);
            *(uint4*)&Ks[row * QPAD + c4 * 4] =
                make_uint4(f2tf32(kv.x), f2tf32(kv.y), f2tf32(kv.z), f2tf32(kv.w));
            *(uint4*)&Vs[row * VPAD + c4 * 4] =
                make_uint4(f2tf32(vv.x), f2tf32(vv.y), f2tf32(vv.z), f2tf32(vv.w));
        }
        __syncthreads();

        // Scores: S(16x64) = Qw(16x64) @ K^T
        float sc[8][4];
        #pragma unroll
        for (int nt = 0; nt < 8; nt++)
            #pragma unroll
            for (int i = 0; i < 4; i++) sc[nt][i] = 0.f;

        #pragma unroll
        for (int k8 = 0; k8 < 8; k8++) {
            int kk = k8 * 8;
            uint32_t a[4];
            a[0] = Qs[(qrow + g) * QPAD + kk + tig];
            a[1] = Qs[(qrow + g + 8) * QPAD + kk + tig];
            a[2] = Qs[(qrow + g) * QPAD + kk + tig + 4];
            a[3] = Qs[(qrow + g + 8) * QPAD + kk + tig + 4];
            #pragma unroll
            for (int nt = 0; nt < 8; nt++) {
                uint32_t bf[2];
                bf[0] = Ks[(nt * 8 + g) * QPAD + kk + tig];
                bf[1] = Ks[(nt * 8 + g) * QPAD + kk + tig + 4];
                mma_tf32(sc[nt], a, bf);
            }
        }

        // Causal mask (only for warps overlapping the diagonal)
        const int r0g = q0 + qrow + g;
        if (k0 + 63 > q0 + qrow) {
            #pragma unroll
            for (int nt = 0; nt < 8; nt++) {
                int cbase = k0 + nt * 8 + 2 * tig;
                if (cbase > r0g)     sc[nt][0] = -1e30f;
                if (cbase + 1 > r0g) sc[nt][1] = -1e30f;
                if (cbase > r0g + 8)     sc[nt][2] = -1e30f;
                if (cbase + 1 > r0g + 8) sc[nt][3] = -1e30f;
            }
        }

        // Online softmax (rows g and g+8)
        float mx0 = -1e30f, mx1 = -1e30f;
        #pragma unroll
        for (int nt = 0; nt < 8; nt++) {
            mx0 = fmaxf(mx0, fmaxf(sc[nt][0], sc[nt][1]));
            mx1 = fmaxf(mx1, fmaxf(sc[nt][2], sc[nt][3]));
        }
        mx0 = fmaxf(mx0, __shfl_xor_sync(0xffffffffu, mx0, 1));
        mx0 = fmaxf(mx0, __shfl_xor_sync(0xffffffffu, mx0, 2));
        mx1 = fmaxf(mx1, __shfl_xor_sync(0xffffffffu, mx1, 1));
        mx1 = fmaxf(mx1, __shfl_xor_sync(0xffffffffu, mx1, 2));

        float mn0 = fmaxf(m0, mx0), mn1 = fmaxf(m1, mx1);
        float cr0 = __expf(m0 - mn0), cr1 = __expf(m1 - mn1);
        float s0 = 0.f, s1 = 0.f;
        #pragma unroll
        for (int nt = 0; nt < 8; nt++) {
            sc[nt][0] = __expf(sc[nt][0] - mn0);
            sc[nt][1] = __expf(sc[nt][1] - mn0);
            sc[nt][2] = __expf(sc[nt][2] - mn1);
            sc[nt][3] = __expf(sc[nt][3] - mn1);
            s0 += sc[nt][0] + sc[nt][1];
            s1 += sc[nt][2] + sc[nt][3];
        }
        s0 += __shfl_xor_sync(0xffffffffu, s0, 1);
        s0 += __shfl_xor_sync(0xffffffffu, s0, 2);
        s1 += __shfl_xor_sync(0xffffffffu, s1, 1);
        s1 += __shfl_xor_sync(0xffffffffu, s1, 2);

        l0 = l0 * cr0 + s0;  m0 = mn0;
        l1 = l1 * cr1 + s1;  m1 = mn1;
        #pragma unroll
        for (int dt = 0; dt < 8; dt++) {
            o[dt][0] *= cr0; o[dt][1] *= cr0;
            o[dt][2] *= cr1; o[dt][3] *= cr1;
        }

        // PV: O(16x64) += P(16x64) @ V(64x64)
        const int src0 = (lane & ~3) | (tig >> 1);
        const int src1 = src0 + 2;
        const bool odd = tig & 1;
        #pragma unroll
        for (int ks = 0; ks < 8; ks++) {
            // C-frag -> A-frag relayout via intra-quad shuffles, then tf32 cvt
            float x00 = __shfl_sync(0xffffffffu, sc[ks][0], src0);
            float x01 = __shfl_sync(0xffffffffu, sc[ks][1], src0);
            float x02 = __shfl_sync(0xffffffffu, sc[ks][2], src0);
            float x03 = __shfl_sync(0xffffffffu, sc[ks][3], src0);
            float x10 = __shfl_sync(0xffffffffu, sc[ks][0], src1);
            float x11 = __shfl_sync(0xffffffffu, sc[ks][1], src1);
            float x12 = __shfl_sync(0xffffffffu, sc[ks][2], src1);
            float x13 = __shfl_sync(0xffffffffu, sc[ks][3], src1);
            uint32_t a[4];
            a[0] = f2tf32(odd ? x01 : x00);
            a[1] = f2tf32(odd ? x03 : x02);
            a[2] = f2tf32(odd ? x11 : x10);
            a[3] = f2tf32(odd ? x13 : x12);
            #pragma unroll
            for (int dt = 0; dt < 8; dt++) {
                uint32_t bf[2];
                bf[0] = Vs[(ks * 8 + tig) * VPAD + dt * 8 + g];
                bf[1] = Vs[(ks * 8 + tig + 4) * VPAD + dt * 8 + g];
                mma_tf32(o[dt], a, bf);
            }
        }
    }

    // Epilogue
    const float inv0 = 1.0f / l0, inv1 = 1.0f / l1;
    const int gr0 = q0 + qrow + g;
    float* Ob = O + (size_t)b * SS * DD + h * HD;
    #pragma unroll
    for (int dt = 0; dt < 8; dt++) {
        int cc = dt * 8 + 2 * tig;
        *(float2*)(Ob + (size_t)gr0 * DD + cc) =
            make_float2(o[dt][0] * inv0, o[dt][1] * inv0);
        *(float2*)(Ob + (size_t)(gr0 + 8) * DD + cc) =
            make_float2(o[dt][2] * inv1, o[dt][3] * inv1);
    }
}

// ---------------------------------------------------------------------------
extern "C" void kernel_launch(void* const* d_in, const int* in_sizes, int n_in,
                              void* d_out, int out_size) {
    const float* x  = (const float*)d_in[0];
    const float* Wq = (const float*)d_in[1];
    const float* Wk = (const float*)d_in[2];
    const float* Wv = (const float*)d_in[3];
    const float* Wo = (const float*)d_in[4];
    const float* bo = (const float*)d_in[5];
    float* out = (float*)d_out;

    float *q, *k, *v, *ctx, *wt;
    cudaGetSymbolAddress((void**)&q,   g_q);
    cudaGetSymbolAddress((void**)&k,   g_k);
    cudaGetSymbolAddress((void**)&v,   g_v);
    cudaGetSymbolAddress((void**)&ctx, g_ctx);
    cudaGetSymbolAddress((void**)&wt,  g_wt);
    float* WqT = wt;
    float* WkT = wt + 1 * DD * DD;
    float* WvT = wt + 2 * DD * DD;
    float* WoT = wt + 3 * DD * DD;

    dim3 tgrid(32, 32), tblk(32, 8);
    transpose1024<<<tgrid, tblk>>>(Wq, WqT);
    transpose1024<<<tgrid, tblk>>>(Wk, WkT);
    transpose1024<<<tgrid, tblk>>>(Wv, WvT);
    transpose1024<<<tgrid, tblk>>>(Wo, WoT);

    dim3 ggrid(GN / 128, MROWS / 128);  // (8, 64)
    gemm_tc<<<ggrid, 256>>>(x, WqT, nullptr, q);
    gemm_tc<<<ggrid, 256>>>(x, WkT, nullptr, k);
    gemm_tc<<<ggrid, 256>>>(x, WvT, nullptr, v);

    cudaFuncSetAttribute(attn_tc, cudaFuncAttributeMaxDynamicSharedMemorySize, ATTN_SMEM);
    attn_tc<<<dim3(SS / 128, HH, BB), 256, ATTN_SMEM>>>(q, k, v, ctx);

    gemm_tc<<<ggrid, 256>>>(ctx, WoT, bo, out);
}

// round 6
// speedup vs baseline: 4.6159x; 1.0794x over previous
#include <cuda_runtime.h>
#include <math.h>
#include <stdint.h>

// Problem constants
#define BB 4
#define SS 2048
#define DD 1024
#define HH 16
#define HD 64
#define MROWS (BB * SS)   // 8192

// Scratch (static device globals — allocation-free per harness rules)
__device__ float g_q[MROWS * DD];
__device__ float g_k[MROWS * DD];
__device__ float g_v[MROWS * DD];
__device__ float g_ctx[MROWS * DD];

extern __shared__ char dynsmem[];

__device__ __forceinline__ uint32_t f2tf32(float f) {
    uint32_t r;
    asm("cvt.rna.tf32.f32 %0, %1;" : "=r"(r) : "f"(f));
    return r;
}

__device__ __forceinline__ void mma_tf32(float* d, const uint32_t* a, const uint32_t* b) {
    asm volatile(
        "mma.sync.aligned.m16n8k8.row.col.f32.tf32.tf32.f32 "
        "{%0,%1,%2,%3}, {%4,%5,%6,%7}, {%8,%9}, {%0,%1,%2,%3};"
        : "+f"(d[0]), "+f"(d[1]), "+f"(d[2]), "+f"(d[3])
        : "r"(a[0]), "r"(a[1]), "r"(a[2]), "r"(a[3]), "r"(b[0]), "r"(b[1]));
}

// ---------------------------------------------------------------------------
// TF32 mma.sync GEMM with register-prefetch pipeline.
// C[M,N] = A[M,K] @ W[K,N] (+ bias). W read directly k-major (no transpose).
// BM=128, BN=128, BK=32. 256 threads = 8 warps (2 M x 4 N), warp tile 64x32.
// Smem: As[m][36] (k fast), Bs[k][132] (n fast).
// ---------------------------------------------------------------------------
#define GK 1024
#define GN 1024
#define APAD 36
#define BPAD 132
#define GEMM_SMEM ((128 * APAD + 32 * BPAD) * 4)   // 35328 B

struct GemmSmem {
    uint32_t As[128 * APAD];
    uint32_t Bs[32 * BPAD];
};

__device__ __forceinline__ void gemm_body(const float* __restrict__ A,
                                          const float* __restrict__ W,
                                          const float* __restrict__ bias,
                                          float* __restrict__ C,
                                          int row0, int col0) {
    GemmSmem* sm = (GemmSmem*)dynsmem;

    const int t    = threadIdx.x;
    const int lane = t & 31;
    const int wid  = t >> 5;
    const int wm   = wid & 1;
    const int wn   = wid >> 1;
    const int g    = lane >> 2;
    const int tig  = lane & 3;

    const int c4 = t & 7;   // float4 slot
    const int r0 = t >> 3;  // 0..31

    float acc[4][4][4];
    #pragma unroll
    for (int mt = 0; mt < 4; mt++)
        #pragma unroll
        for (int nt = 0; nt < 4; nt++)
            #pragma unroll
            for (int i = 0; i < 4; i++) acc[mt][nt][i] = 0.f;

    // prefetch registers
    float4 pa[4], pb[4];

    // A: rows r0+32i of this M-tile, k-slot c4.  W: k-row r0, float4 cols c4+8i.
    const float* Ap = A + (size_t)(row0 + r0) * GK + c4 * 4;
    const float* Wp = W + (size_t)r0 * GN + col0 + c4 * 4;

    // preload tile 0
    #pragma unroll
    for (int i = 0; i < 4; i++) {
        pa[i] = *(const float4*)(Ap + (size_t)(i * 32) * GK);
        pb[i] = *(const float4*)(Wp + i * 32);
    }

    for (int c = 0; c < GK / 32; c++) {
        // store prefetched tile into smem (with tf32 cvt)
        #pragma unroll
        for (int i = 0; i < 4; i++) {
            int r = r0 + i * 32;
            *(uint4*)&sm->As[r * APAD + c4 * 4] =
                make_uint4(f2tf32(pa[i].x), f2tf32(pa[i].y), f2tf32(pa[i].z), f2tf32(pa[i].w));
            *(uint4*)&sm->Bs[r0 * BPAD + (c4 + 8 * i) * 4] =
                make_uint4(f2tf32(pb[i].x), f2tf32(pb[i].y), f2tf32(pb[i].z), f2tf32(pb[i].w));
        }
        __syncthreads();

        // issue next tile's global loads (latency hidden by MMAs below)
        if (c + 1 < GK / 32) {
            const float* An = Ap + (c + 1) * 32;
            const float* Wn = W + (size_t)((c + 1) * 32 + r0) * GN + col0 + c4 * 4;
            #pragma unroll
            for (int i = 0; i < 4; i++) {
                pa[i] = *(const float4*)(An + (size_t)(i * 32) * GK);
                pb[i] = *(const float4*)(Wn + i * 32);
            }
        }

        #pragma unroll
        for (int kk = 0; kk < 32; kk += 8) {
            uint32_t af[4][4], bf[4][2];
            #pragma unroll
            for (int mt = 0; mt < 4; mt++) {
                int rbase = wm * 64 + mt * 16;
                af[mt][0] = sm->As[(rbase + g) * APAD + kk + tig];
                af[mt][1] = sm->As[(rbase + g + 8) * APAD + kk + tig];
                af[mt][2] = sm->As[(rbase + g) * APAD + kk + tig + 4];
                af[mt][3] = sm->As[(rbase + g + 8) * APAD + kk + tig + 4];
            }
            #pragma unroll
            for (int nt = 0; nt < 4; nt++) {
                int nbase = wn * 32 + nt * 8;
                bf[nt][0] = sm->Bs[(kk + tig) * BPAD + nbase + g];
                bf[nt][1] = sm->Bs[(kk + tig + 4) * BPAD + nbase + g];
            }
            #pragma unroll
            for (int mt = 0; mt < 4; mt++)
                #pragma unroll
                for (int nt = 0; nt < 4; nt++)
                    mma_tf32(acc[mt][nt], af[mt], bf[nt]);
        }
        __syncthreads();
    }

    #pragma unroll
    for (int mt = 0; mt < 4; mt++) {
        #pragma unroll
        for (int nt = 0; nt < 4; nt++) {
            int r1 = row0 + wm * 64 + mt * 16 + g;
            int cc = col0 + wn * 32 + nt * 8 + 2 * tig;
            float2 o0 = make_float2(acc[mt][nt][0], acc[mt][nt][1]);
            float2 o1 = make_float2(acc[mt][nt][2], acc[mt][nt][3]);
            if (bias) {
                float2 bv = *(const float2*)(bias + cc);
                o0.x += bv.x; o0.y += bv.y;
                o1.x += bv.x; o1.y += bv.y;
            }
            *(float2*)(C + (size_t)r1 * GN + cc)       = o0;
            *(float2*)(C + (size_t)(r1 + 8) * GN + cc) = o1;
        }
    }
}

// Fused QKV: grid.x = 24 -> (weight, col-tile)
__global__ __launch_bounds__(256, 2) void gemm_qkv(const float* __restrict__ A,
                                                   const float* __restrict__ W0,
                                                   const float* __restrict__ W1,
                                                   const float* __restrict__ W2,
                                                   float* __restrict__ C0,
                                                   float* __restrict__ C1,
                                                   float* __restrict__ C2) {
    int w = blockIdx.x >> 3;
    int col0 = (blockIdx.x & 7) * 128;
    int row0 = blockIdx.y * 128;
    const float* W = (w == 0) ? W0 : (w == 1) ? W1 : W2;
    float* C       = (w == 0) ? C0 : (w == 1) ? C1 : C2;
    gemm_body(A, W, nullptr, C, row0, col0);
}

__global__ __launch_bounds__(256, 2) void gemm_single(const float* __restrict__ A,
                                                      const float* __restrict__ W,
                                                      const float* __restrict__ bias,
                                                      float* __restrict__ C) {
    gemm_body(A, W, bias, C, blockIdx.y * 128, blockIdx.x * 128);
}

// ---------------------------------------------------------------------------
// Tensor-core flash attention (tf32 mma.sync), causal. exp2-domain softmax.
// ---------------------------------------------------------------------------
#define QPAD 68
#define VPAD 72
#define ATTN_SMEM ((128 * QPAD + 64 * QPAD + 64 * VPAD) * 4)

__global__ __launch_bounds__(256, 2) void attn_tc(const float* __restrict__ Q,
                                                  const float* __restrict__ K,
                                                  const float* __restrict__ V,
                                                  float* __restrict__ O) {
    uint32_t* Qs = (uint32_t*)dynsmem;           // [128][QPAD]
    uint32_t* Ks = Qs + 128 * QPAD;              // [64][QPAD]
    uint32_t* Vs = Ks + 64 * QPAD;               // [64][VPAD]

    const int t    = threadIdx.x;
    const int lane = t & 31;
    const int wid  = t >> 5;
    const int g    = lane >> 2;
    const int tig  = lane & 3;

    const int qb = gridDim.x - 1 - blockIdx.x;
    const int h  = blockIdx.y, b = blockIdx.z;
    const int q0 = qb * 128;

    const float* Qbase = Q + (size_t)b * SS * DD + h * HD;
    const float* Kbase = K + (size_t)b * SS * DD + h * HD;
    const float* Vbase = V + (size_t)b * SS * DD + h * HD;

    // Stage Q tile (128x64), tf32, pre-scaled by log2(e)/8 (exp2 domain)
    {
        const float sc = 0.125f * 1.4426950408889634f;
        #pragma unroll
        for (int i = 0; i < 8; i++) {
            int idx = t + i * 256;
            int row = idx >> 4, c4 = idx & 15;
            float4 v = *(const float4*)(Qbase + (size_t)(q0 + row) * DD + c4 * 4);
            *(uint4*)&Qs[row * QPAD + c4 * 4] =
                make_uint4(f2tf32(v.x * sc), f2tf32(v.y * sc),
                           f2tf32(v.z * sc), f2tf32(v.w * sc));
        }
    }

    float o[8][4];
    #pragma unroll
    for (int dt = 0; dt < 8; dt++)
        #pragma unroll
        for (int i = 0; i < 4; i++) o[dt][i] = 0.f;
    float m0 = -1e30f, m1 = -1e30f, l0 = 0.f, l1 = 0.f;

    const int qrow = wid * 16;
    const int ntiles = 2 * qb + 2;

    for (int kt = 0; kt < ntiles; kt++) {
        const int k0 = kt * 64;
        __syncthreads();

        #pragma unroll
        for (int i = 0; i < 4; i++) {
            int idx = t + i * 256;
            int row = idx >> 4, c4 = idx & 15;
            float4 kv = *(const float4*)(Kbase + (size_t)(k0 + row) * DD + c4 * 4);
            float4 vv = *(const float4*)(Vbase + (size_t)(k0 + row) * DD + c4 * 4);
            *(uint4*)&Ks[row * QPAD + c4 * 4] =
                make_uint4(f2tf32(kv.x), f2tf32(kv.y), f2tf32(kv.z), f2tf32(kv.w));
            *(uint4*)&Vs[row * VPAD + c4 * 4] =
                make_uint4(f2tf32(vv.x), f2tf32(vv.y), f2tf32(vv.z), f2tf32(vv.w));
        }
        __syncthreads();

        float sc[8][4];
        #pragma unroll
        for (int nt = 0; nt < 8; nt++)
            #pragma unroll
            for (int i = 0; i < 4; i++) sc[nt][i] = 0.f;

        #pragma unroll
        for (int k8 = 0; k8 < 8; k8++) {
            int kk = k8 * 8;
            uint32_t a[4];
            a[0] = Qs[(qrow + g) * QPAD + kk + tig];
            a[1] = Qs[(qrow + g + 8) * QPAD + kk + tig];
            a[2] = Qs[(qrow + g) * QPAD + kk + tig + 4];
            a[3] = Qs[(qrow + g + 8) * QPAD + kk + tig + 4];
            #pragma unroll
            for (int nt = 0; nt < 8; nt++) {
                uint32_t bf[2];
                bf[0] = Ks[(nt * 8 + g) * QPAD + kk + tig];
                bf[1] = Ks[(nt * 8 + g) * QPAD + kk + tig + 4];
                mma_tf32(sc[nt], a, bf);
            }
        }

        const int r0g = q0 + qrow + g;
        if (k0 + 63 > q0 + qrow) {
            #pragma unroll
            for (int nt = 0; nt < 8; nt++) {
                int cbase = k0 + nt * 8 + 2 * tig;
                if (cbase > r0g)     sc[nt][0] = -1e30f;
                if (cbase + 1 > r0g) sc[nt][1] = -1e30f;
                if (cbase > r0g + 8)     sc[nt][2] = -1e30f;
                if (cbase + 1 > r0g + 8) sc[nt][3] = -1e30f;
            }
        }

        float mx0 = -1e30f, mx1 = -1e30f;
        #pragma unroll
        for (int nt = 0; nt < 8; nt++) {
            mx0 = fmaxf(mx0, fmaxf(sc[nt][0], sc[nt][1]));
            mx1 = fmaxf(mx1, fmaxf(sc[nt][2], sc[nt][3]));
        }
        mx0 = fmaxf(mx0, __shfl_xor_sync(0xffffffffu, mx0, 1));
        mx0 = fmaxf(mx0, __shfl_xor_sync(0xffffffffu, mx0, 2));
        mx1 = fmaxf(mx1, __shfl_xor_sync(0xffffffffu, mx1, 1));
        mx1 = fmaxf(mx1, __shfl_xor_sync(0xffffffffu, mx1, 2));

        float mn0 = fmaxf(m0, mx0), mn1 = fmaxf(m1, mx1);
        float cr0 = exp2f(m0 - mn0), cr1 = exp2f(m1 - mn1);
        float s0 = 0.f, s1 = 0.f;
        #pragma unroll
        for (int nt = 0; nt < 8; nt++) {
            sc[nt][0] = exp2f(sc[nt][0] - mn0);
            sc[nt][1] = exp2f(sc[nt][1] - mn0);
            sc[nt][2] = exp2f(sc[nt][2] - mn1);
            sc[nt][3] = exp2f(sc[nt][3] - mn1);
            s0 += sc[nt][0] + sc[nt][1];
            s1 += sc[nt][2] + sc[nt][3];
        }
        s0 += __shfl_xor_sync(0xffffffffu, s0, 1);
        s0 += __shfl_xor_sync(0xffffffffu, s0, 2);
        s1 += __shfl_xor_sync(0xffffffffu, s1, 1);
        s1 += __shfl_xor_sync(0xffffffffu, s1, 2);

        l0 = l0 * cr0 + s0;  m0 = mn0;
        l1 = l1 * cr1 + s1;  m1 = mn1;
        #pragma unroll
        for (int dt = 0; dt < 8; dt++) {
            o[dt][0] *= cr0; o[dt][1] *= cr0;
            o[dt][2] *= cr1; o[dt][3] *= cr1;
        }

        const int src0 = (lane & ~3) | (tig >> 1);
        const int src1 = src0 + 2;
        const bool odd = tig & 1;
        #pragma unroll
        for (int ks = 0; ks < 8; ks++) {
            float x00 = __shfl_sync(0xffffffffu, sc[ks][0], src0);
            float x01 = __shfl_sync(0xffffffffu, sc[ks][1], src0);
            float x02 = __shfl_sync(0xffffffffu, sc[ks][2], src0);
            float x03 = __shfl_sync(0xffffffffu, sc[ks][3], src0);
            float x10 = __shfl_sync(0xffffffffu, sc[ks][0], src1);
            float x11 = __shfl_sync(0xffffffffu, sc[ks][1], src1);
            float x12 = __shfl_sync(0xffffffffu, sc[ks][2], src1);
            float x13 = __shfl_sync(0xffffffffu, sc[ks][3], src1);
            uint32_t a[4];
            a[0] = f2tf32(odd ? x01 : x00);
            a[1] = f2tf32(odd ? x03 : x02);
            a[2] = f2tf32(odd ? x11 : x10);
            a[3] = f2tf32(odd ? x13 : x12);
            #pragma unroll
            for (int dt = 0; dt < 8; dt++) {
                uint32_t bf[2];
                bf[0] = Vs[(ks * 8 + tig) * VPAD + dt * 8 + g];
                bf[1] = Vs[(ks * 8 + tig + 4) * VPAD + dt * 8 + g];
                mma_tf32(o[dt], a, bf);
            }
        }
    }

    const float inv0 = 1.0f / l0, inv1 = 1.0f / l1;
    const int gr0 = q0 + qrow + g;
    float* Ob = O + (size_t)b * SS * DD + h * HD;
    #pragma unroll
    for (int dt = 0; dt < 8; dt++) {
        int cc = dt * 8 + 2 * tig;
        *(float2*)(Ob + (size_t)gr0 * DD + cc) =
            make_float2(o[dt][0] * inv0, o[dt][1] * inv0);
        *(float2*)(Ob + (size_t)(gr0 + 8) * DD + cc) =
            make_float2(o[dt][2] * inv1, o[dt][3] * inv1);
    }
}

// ---------------------------------------------------------------------------
extern "C" void kernel_launch(void* const* d_in, const int* in_sizes, int n_in,
                              void* d_out, int out_size) {
    const float* x  = (const float*)d_in[0];
    const float* Wq = (const float*)d_in[1];
    const float* Wk = (const float*)d_in[2];
    const float* Wv = (const float*)d_in[3];
    const float* Wo = (const float*)d_in[4];
    const float* bo = (const float*)d_in[5];
    float* out = (float*)d_out;

    float *q, *k, *v, *ctx;
    cudaGetSymbolAddress((void**)&q,   g_q);
    cudaGetSymbolAddress((void**)&k,   g_k);
    cudaGetSymbolAddress((void**)&v,   g_v);
    cudaGetSymbolAddress((void**)&ctx, g_ctx);

    cudaFuncSetAttribute(gemm_qkv, cudaFuncAttributeMaxDynamicSharedMemorySize, GEMM_SMEM);
    cudaFuncSetAttribute(gemm_single, cudaFuncAttributeMaxDynamicSharedMemorySize, GEMM_SMEM);
    cudaFuncSetAttribute(attn_tc, cudaFuncAttributeMaxDynamicSharedMemorySize, ATTN_SMEM);

    gemm_qkv<<<dim3(24, MROWS / 128), 256, GEMM_SMEM>>>(x, Wq, Wk, Wv, q, k, v);

    attn_tc<<<dim3(SS / 128, HH, BB), 256, ATTN_SMEM>>>(q, k, v, ctx);

    gemm_single<<<dim3(8, MROWS / 128), 256, GEMM_SMEM>>>(ctx, Wo, bo, out);
}

// round 8
// speedup vs baseline: 5.1318x; 1.1118x over previous
#include <cuda_runtime.h>
#include <math.h>
#include <stdint.h>

// Problem constants
#define BB 4
#define SS 2048
#define DD 1024
#define HH 16
#define HD 64
#define MROWS (BB * SS)   // 8192

// Scratch (static device globals — allocation-free per harness rules)
__device__ float g_q[MROWS * DD];
__device__ float g_k[MROWS * DD];
__device__ float g_v[MROWS * DD];
__device__ float g_ctx[MROWS * DD];

extern __shared__ char dynsmem[];

__device__ __forceinline__ uint32_t f2tf32(float f) {
    uint32_t r;
    asm("cvt.rna.tf32.f32 %0, %1;" : "=r"(r) : "f"(f));
    return r;
}

__device__ __forceinline__ void mma_tf32(float* d, const uint32_t* a, const uint32_t* b) {
    asm volatile(
        "mma.sync.aligned.m16n8k8.row.col.f32.tf32.tf32.f32 "
        "{%0,%1,%2,%3}, {%4,%5,%6,%7}, {%8,%9}, {%0,%1,%2,%3};"
        : "+f"(d[0]), "+f"(d[1]), "+f"(d[2]), "+f"(d[3])
        : "r"(a[0]), "r"(a[1]), "r"(a[2]), "r"(a[3]), "r"(b[0]), "r"(b[1]));
}

__device__ __forceinline__ void ldsm4(uint32_t* r, uint32_t addr) {
    asm volatile("ldmatrix.sync.aligned.m8n8.x4.shared.b16 {%0,%1,%2,%3}, [%4];"
                 : "=r"(r[0]), "=r"(r[1]), "=r"(r[2]), "=r"(r[3]) : "r"(addr));
}

// ---------------------------------------------------------------------------
// TF32 mma.sync GEMM, register-prefetch pipeline + ldmatrix fragment loads.
// C[M,N] = A[M,K] @ W[K,N] (+ bias). BM=128, BN=128, BK=32. 256 thr, 8 warps.
// As[m][36] k-major; Bs[n][36] n-major (transposed during load).
// ---------------------------------------------------------------------------
#define GK 1024
#define GN 1024
#define APAD 36
#define GEMM_SMEM ((128 * APAD + 128 * APAD) * 4)   // 36864 B

struct GemmSmem {
    uint32_t As[128 * APAD];
    uint32_t Bs[128 * APAD];
};

__device__ __forceinline__ void gemm_body(const float* __restrict__ A,
                                          const float* __restrict__ W,
                                          const float* __restrict__ bias,
                                          float* __restrict__ C,
                                          int row0, int col0) {
    GemmSmem* sm = (GemmSmem*)dynsmem;

    const int t    = threadIdx.x;
    const int lane = t & 31;
    const int wid  = t >> 5;
    const int wm   = wid & 1;
    const int wn   = wid >> 1;

    // A global mapping: rows r0+32i, float4 slot c4
    const int c4 = t & 7;
    const int r0 = t >> 3;
    // B global mapping: column n per thread, k half
    const int bn  = t & 127;
    const int bkh = (t >> 7) * 16;

    float acc[4][4][4];
    #pragma unroll
    for (int mt = 0; mt < 4; mt++)
        #pragma unroll
        for (int nt = 0; nt < 4; nt++)
            #pragma unroll
            for (int i = 0; i < 4; i++) acc[mt][nt][i] = 0.f;

    float4 pa[4];
    float  pb[16];

    const float* Ap = A + (size_t)(row0 + r0) * GK + c4 * 4;
    const float* Wp = W + col0 + bn;

    // preload tile 0
    #pragma unroll
    for (int i = 0; i < 4; i++)
        pa[i] = *(const float4*)(Ap + (size_t)(i * 32) * GK);
    #pragma unroll
    for (int q = 0; q < 16; q++)
        pb[q] = Wp[(size_t)(bkh + q) * GN];

    // ldmatrix fragment addresses
    uint32_t As_s = (uint32_t)__cvta_generic_to_shared(sm->As);
    uint32_t Bs_s = (uint32_t)__cvta_generic_to_shared(sm->Bs);
    const int l15  = lane & 15;
    const int ahi  = (lane >> 4) * 4;                        // word offset (0/4)
    const int nrow = ((lane >> 4) << 3) + (lane & 7);        // 0..15
    const int kadd = ((lane >> 3) & 1) * 4;                  // word offset (0/4)
    uint32_t aAddr[4], bAddr[2];
    #pragma unroll
    for (int mt = 0; mt < 4; mt++)
        aAddr[mt] = As_s + (uint32_t)(((wm * 64 + mt * 16 + l15) * APAD + ahi) * 4);
    #pragma unroll
    for (int p = 0; p < 2; p++)
        bAddr[p] = Bs_s + (uint32_t)(((wn * 32 + p * 16 + nrow) * APAD + kadd) * 4);

    for (int c = 0; c < GK / 32; c++) {
        // store prefetched tile (tf32 cvt). A: k-major rows. B: n-major rows.
        #pragma unroll
        for (int i = 0; i < 4; i++) {
            int r = r0 + i * 32;
            *(uint4*)&sm->As[r * APAD + c4 * 4] =
                make_uint4(f2tf32(pa[i].x), f2tf32(pa[i].y), f2tf32(pa[i].z), f2tf32(pa[i].w));
        }
        #pragma unroll
        for (int q4 = 0; q4 < 4; q4++) {
            *(uint4*)&sm->Bs[bn * APAD + bkh + q4 * 4] =
                make_uint4(f2tf32(pb[q4 * 4 + 0]), f2tf32(pb[q4 * 4 + 1]),
                           f2tf32(pb[q4 * 4 + 2]), f2tf32(pb[q4 * 4 + 3]));
        }
        __syncthreads();

        // issue next tile's global loads (hidden behind MMAs)
        if (c + 1 < GK / 32) {
            const float* An = Ap + (c + 1) * 32;
            const float* Wn = Wp + (size_t)((c + 1) * 32 + bkh) * GN;
            #pragma unroll
            for (int i = 0; i < 4; i++)
                pa[i] = *(const float4*)(An + (size_t)(i * 32) * GK);
            #pragma unroll
            for (int q = 0; q < 16; q++)
                pb[q] = Wn[(size_t)q * GN];
        }

        #pragma unroll
        for (int kk = 0; kk < 32; kk += 8) {
            uint32_t af[4][4], bq[2][4];
            #pragma unroll
            for (int mt = 0; mt < 4; mt++) ldsm4(af[mt], aAddr[mt] + kk * 4);
            #pragma unroll
            for (int p = 0; p < 2; p++)    ldsm4(bq[p], bAddr[p] + kk * 4);
            #pragma unroll
            for (int mt = 0; mt < 4; mt++)
                #pragma unroll
                for (int nt = 0; nt < 4; nt++)
                    mma_tf32(acc[mt][nt], af[mt], &bq[nt >> 1][(nt & 1) * 2]);
        }
        __syncthreads();
    }

    const int ge = lane >> 2, te = lane & 3;
    #pragma unroll
    for (int mt = 0; mt < 4; mt++) {
        #pragma unroll
        for (int nt = 0; nt < 4; nt++) {
            int r1 = row0 + wm * 64 + mt * 16 + ge;
            int cc = col0 + wn * 32 + nt * 8 + 2 * te;
            float2 o0 = make_float2(acc[mt][nt][0], acc[mt][nt][1]);
            float2 o1 = make_float2(acc[mt][nt][2], acc[mt][nt][3]);
            if (bias) {
                float2 bv = *(const float2*)(bias + cc);
                o0.x += bv.x; o0.y += bv.y;
                o1.x += bv.x; o1.y += bv.y;
            }
            *(float2*)(C + (size_t)r1 * GN + cc)       = o0;
            *(float2*)(C + (size_t)(r1 + 8) * GN + cc) = o1;
        }
    }
}

// Fused QKV: grid.x = 24 -> (weight, col-tile)
__global__ __launch_bounds__(256, 2) void gemm_qkv(const float* __restrict__ A,
                                                   const float* __restrict__ W0,
                                                   const float* __restrict__ W1,
                                                   const float* __restrict__ W2,
                                                   float* __restrict__ C0,
                                                   float* __restrict__ C1,
                                                   float* __restrict__ C2) {
    int w = blockIdx.x >> 3;
    int col0 = (blockIdx.x & 7) * 128;
    int row0 = blockIdx.y * 128;
    const float* W = (w == 0) ? W0 : (w == 1) ? W1 : W2;
    float* C       = (w == 0) ? C0 : (w == 1) ? C1 : C2;
    gemm_body(A, W, nullptr, C, row0, col0);
}

__global__ __launch_bounds__(256, 2) void gemm_single(const float* __restrict__ A,
                                                      const float* __restrict__ W,
                                                      const float* __restrict__ bias,
                                                      float* __restrict__ C) {
    gemm_body(A, W, bias, C, blockIdx.y * 128, blockIdx.x * 128);
}

// ---------------------------------------------------------------------------
// Tensor-core flash attention (tf32 mma.sync), causal, exp2-domain softmax.
// QK fragment loads via ldmatrix (layouts already compatible).
// ---------------------------------------------------------------------------
#define QPAD 68
#define VPAD 72
#define ATTN_SMEM ((128 * QPAD + 64 * QPAD + 64 * VPAD) * 4)

__global__ __launch_bounds__(256, 2) void attn_tc(const float* __restrict__ Q,
                                                  const float* __restrict__ K,
                                                  const float* __restrict__ V,
                                                  float* __restrict__ O) {
    uint32_t* Qs = (uint32_t*)dynsmem;           // [128][QPAD]
    uint32_t* Ks = Qs + 128 * QPAD;              // [64][QPAD]  rows = key
    uint32_t* Vs = Ks + 64 * QPAD;               // [64][VPAD]  rows = key

    const int t    = threadIdx.x;
    const int lane = t & 31;
    const int wid  = t >> 5;
    const int g    = lane >> 2;
    const int tig  = lane & 3;

    const int qb = gridDim.x - 1 - blockIdx.x;
    const int h  = blockIdx.y, b = blockIdx.z;
    const int q0 = qb * 128;

    const float* Qbase = Q + (size_t)b * SS * DD + h * HD;
    const float* Kbase = K + (size_t)b * SS * DD + h * HD;
    const float* Vbase = V + (size_t)b * SS * DD + h * HD;

    // Stage Q tile (128x64), tf32, pre-scaled by log2(e)/8 (exp2 domain)
    {
        const float sc = 0.125f * 1.4426950408889634f;
        #pragma unroll
        for (int i = 0; i < 8; i++) {
            int idx = t + i * 256;
            int row = idx >> 4, c4 = idx & 15;
            float4 v = *(const float4*)(Qbase + (size_t)(q0 + row) * DD + c4 * 4);
            *(uint4*)&Qs[row * QPAD + c4 * 4] =
                make_uint4(f2tf32(v.x * sc), f2tf32(v.y * sc),
                           f2tf32(v.z * sc), f2tf32(v.w * sc));
        }
    }

    float o[8][4];
    #pragma unroll
    for (int dt = 0; dt < 8; dt++)
        #pragma unroll
        for (int i = 0; i < 4; i++) o[dt][i] = 0.f;
    float m0 = -1e30f, m1 = -1e30f, l0 = 0.f, l1 = 0.f;

    const int qrow = wid * 16;
    const int ntiles = 2 * qb + 2;

    // ldmatrix addresses for Q (A-frag) and K (B-frag)
    uint32_t Qs_s = (uint32_t)__cvta_generic_to_shared(Qs);
    uint32_t Ks_s = (uint32_t)__cvta_generic_to_shared(Ks);
    const int l15  = lane & 15;
    const int ahi  = (lane >> 4) * 4;
    const int nrow = ((lane >> 4) << 3) + (lane & 7);
    const int kadd = ((lane >> 3) & 1) * 4;
    uint32_t qAddr = Qs_s + (uint32_t)(((qrow + l15) * QPAD + ahi) * 4);
    uint32_t kAddr[4];
    #pragma unroll
    for (int p = 0; p < 4; p++)
        kAddr[p] = Ks_s + (uint32_t)(((p * 16 + nrow) * QPAD + kadd) * 4);

    for (int kt = 0; kt < ntiles; kt++) {
        const int k0 = kt * 64;
        __syncthreads();

        #pragma unroll
        for (int i = 0; i < 4; i++) {
            int idx = t + i * 256;
            int row = idx >> 4, c4 = idx & 15;
            float4 kv = *(const float4*)(Kbase + (size_t)(k0 + row) * DD + c4 * 4);
            float4 vv = *(const float4*)(Vbase + (size_t)(k0 + row) * DD + c4 * 4);
            *(uint4*)&Ks[row * QPAD + c4 * 4] =
                make_uint4(f2tf32(kv.x), f2tf32(kv.y), f2tf32(kv.z), f2tf32(kv.w));
            *(uint4*)&Vs[row * VPAD + c4 * 4] =
                make_uint4(f2tf32(vv.x), f2tf32(vv.y), f2tf32(vv.z), f2tf32(vv.w));
        }
        __syncthreads();

        float sc[8][4];
        #pragma unroll
        for (int nt = 0; nt < 8; nt++)
            #pragma unroll
            for (int i = 0; i < 4; i++) sc[nt][i] = 0.f;

        #pragma unroll
        for (int k8 = 0; k8 < 8; k8++) {
            int kk = k8 * 8;
            uint32_t a[4], bq[4][4];
            ldsm4(a, qAddr + kk * 4);
            #pragma unroll
            for (int p = 0; p < 4; p++) ldsm4(bq[p], kAddr[p] + kk * 4);
            #pragma unroll
            for (int nt = 0; nt < 8; nt++)
                mma_tf32(sc[nt], a, &bq[nt >> 1][(nt & 1) * 2]);
        }

        const int r0g = q0 + qrow + g;
        if (k0 + 63 > q0 + qrow) {
            #pragma unroll
            for (int nt = 0; nt < 8; nt++) {
                int cbase = k0 + nt * 8 + 2 * tig;
                if (cbase > r0g)     sc[nt][0] = -1e30f;
                if (cbase + 1 > r0g) sc[nt][1] = -1e30f;
                if (cbase > r0g + 8)     sc[nt][2] = -1e30f;
                if (cbase + 1 > r0g + 8) sc[nt][3] = -1e30f;
            }
        }

        float mx0 = -1e30f, mx1 = -1e30f;
        #pragma unroll
        for (int nt = 0; nt < 8; nt++) {
            mx0 = fmaxf(mx0, fmaxf(sc[nt][0], sc[nt][1]));
            mx1 = fmaxf(mx1, fmaxf(sc[nt][2], sc[nt][3]));
        }
        mx0 = fmaxf(mx0, __shfl_xor_sync(0xffffffffu, mx0, 1));
        mx0 = fmaxf(mx0, __shfl_xor_sync(0xffffffffu, mx0, 2));
        mx1 = fmaxf(mx1, __shfl_xor_sync(0xffffffffu, mx1, 1));
        mx1 = fmaxf(mx1, __shfl_xor_sync(0xffffffffu, mx1, 2));

        float mn0 = fmaxf(m0, mx0), mn1 = fmaxf(m1, mx1);
        float cr0 = exp2f(m0 - mn0), cr1 = exp2f(m1 - mn1);
        float s0 = 0.f, s1 = 0.f;
        #pragma unroll
        for (int nt = 0; nt < 8; nt++) {
            sc[nt][0] = exp2f(sc[nt][0] - mn0);
            sc[nt][1] = exp2f(sc[nt][1] - mn0);
            sc[nt][2] = exp2f(sc[nt][2] - mn1);
            sc[nt][3] = exp2f(sc[nt][3] - mn1);
            s0 += sc[nt][0] + sc[nt][1];
            s1 += sc[nt][2] + sc[nt][3];
        }
        s0 += __shfl_xor_sync(0xffffffffu, s0, 1);
        s0 += __shfl_xor_sync(0xffffffffu, s0, 2);
        s1 += __shfl_xor_sync(0xffffffffu, s1, 1);
        s1 += __shfl_xor_sync(0xffffffffu, s1, 2);

        l0 = l0 * cr0 + s0;  m0 = mn0;
        l1 = l1 * cr1 + s1;  m1 = mn1;
        #pragma unroll
        for (int dt = 0; dt < 8; dt++) {
            o[dt][0] *= cr0; o[dt][1] *= cr0;
            o[dt][2] *= cr1; o[dt][3] *= cr1;
        }

        const int src0 = (lane & ~3) | (tig >> 1);
        const int src1 = src0 + 2;
        const bool odd = tig & 1;
        #pragma unroll
        for (int ks = 0; ks < 8; ks++) {
            float x00 = __shfl_sync(0xffffffffu, sc[ks][0], src0);
            float x01 = __shfl_sync(0xffffffffu, sc[ks][1], src0);
            float x02 = __shfl_sync(0xffffffffu, sc[ks][2], src0);
            float x03 = __shfl_sync(0xffffffffu, sc[ks][3], src0);
            float x10 = __shfl_sync(0xffffffffu, sc[ks][0], src1);
            float x11 = __shfl_sync(0xffffffffu, sc[ks][1], src1);
            float x12 = __shfl_sync(0xffffffffu, sc[ks][2], src1);
            float x13 = __shfl_sync(0xffffffffu, sc[ks][3], src1);
            uint32_t a[4];
            a[0] = f2tf32(odd ? x01 : x00);
            a[1] = f2tf32(odd ? x03 : x02);
            a[2] = f2tf32(odd ? x11 : x10);
            a[3] = f2tf32(odd ? x13 : x12);
            #pragma unroll
            for (int dt = 0; dt < 8; dt++) {
                uint32_t bf[2];
                bf[0] = Vs[(ks * 8 + tig) * VPAD + dt * 8 + g];
                bf[1] = Vs[(ks * 8 + tig + 4) * VPAD + dt * 8 + g];
                mma_tf32(o[dt], a, bf);
            }
        }
    }

    const float inv0 = 1.0f / l0, inv1 = 1.0f / l1;
    const int gr0 = q0 + qrow + g;
    float* Ob = O + (size_t)b * SS * DD + h * HD;
    #pragma unroll
    for (int dt = 0; dt < 8; dt++) {
        int cc = dt * 8 + 2 * tig;
        *(float2*)(Ob + (size_t)gr0 * DD + cc) =
            make_float2(o[dt][0] * inv0, o[dt][1] * inv0);
        *(float2*)(Ob + (size_t)(gr0 + 8) * DD + cc) =
            make_float2(o[dt][2] * inv1, o[dt][3] * inv1);
    }
}

// ---------------------------------------------------------------------------
extern "C" void kernel_launch(void* const* d_in, const int* in_sizes, int n_in,
                              void* d_out, int out_size) {
    const float* x  = (const float*)d_in[0];
    const float* Wq = (const float*)d_in[1];
    const float* Wk = (const float*)d_in[2];
    const float* Wv = (const float*)d_in[3];
    const float* Wo = (const float*)d_in[4];
    const float* bo = (const float*)d_in[5];
    float* out = (float*)d_out;

    float *q, *k, *v, *ctx;
    cudaGetSymbolAddress((void**)&q,   g_q);
    cudaGetSymbolAddress((void**)&k,   g_k);
    cudaGetSymbolAddress((void**)&v,   g_v);
    cudaGetSymbolAddress((void**)&ctx, g_ctx);

    cudaFuncSetAttribute(gemm_qkv, cudaFuncAttributeMaxDynamicSharedMemorySize, GEMM_SMEM);
    cudaFuncSetAttribute(gemm_single, cudaFuncAttributeMaxDynamicSharedMemorySize, GEMM_SMEM);
    cudaFuncSetAttribute(attn_tc, cudaFuncAttributeMaxDynamicSharedMemorySize, ATTN_SMEM);

    gemm_qkv<<<dim3(24, MROWS / 128), 256, GEMM_SMEM>>>(x, Wq, Wk, Wv, q, k, v);

    attn_tc<<<dim3(SS / 128, HH, BB), 256, ATTN_SMEM>>>(q, k, v, ctx);

    gemm_single<<<dim3(8, MROWS / 128), 256, GEMM_SMEM>>>(ctx, Wo, bo, out);
}